// round 17
// baseline (speedup 1.0000x reference)
#include <cuda_runtime.h>
#include <cuda_fp16.h>
#include <cstdint>

#define BB 32
#define TT 4096
#define PP 512
#define WW 128
#define NMEL 80
#define FILT 256
#define PDIM 64
#define KK 9
#define PAD 4

// ---- conv2 (M=128 x N=128), K-chunk 64 ----
#define STR2 72
#define A_ROWS 136
#define A_CP2 (A_ROWS * STR2)          // 9792 elems
#define B_CP2 (128 * STR2)             // 9216 elems
#define OFF_B2 (2 * A_CP2)             // 19584
#define CONV2_SMEM ((OFF_B2 + 3 * B_CP2) * 2)   // 94464 B -> 2 CTAs/SM

// ---- conv1 fused (M=64 x N=256), single K-chunk of 80 ----
#define C1_STR 88
#define C1_AROWS 72
#define C1_ACP (C1_AROWS * C1_STR)     // 6336 elems
#define C1_BCP (FILT * C1_STR)         // 22528 elems
#define C1_OFFB C1_ACP                 // 6336
#define CONV1_SMEM ((C1_OFFB + 2 * C1_BCP) * 2)  // 102784 B -> 2 CTAs/SM

// ---------------- device scratch ----------------------------------------------------
__device__ __half g_melhi[(size_t)BB * TT * 96];
__device__ __half g_x1hi[(size_t)BB * TT * FILT];
__device__ __half g_craw[(size_t)BB * TT * FILT];    // fp16: bias+relu applied
__device__ __half g_w1h[KK * FILT * 96];
__device__ __half g_w2h[KK * FILT * FILT];
__device__ float g_ph[(size_t)BB * PP * FILT];
__device__ float g_wd[(size_t)BB * WW * FILT];
__device__ float g_z [(size_t)BB * WW * PDIM];
__device__ int   g_pcum[BB * PP];
__device__ int   g_wcum[BB * WW];

// ---------------- helpers ------------------------------------------------------------
__device__ __forceinline__ uint32_t smem_u32(const void* p) {
    return (uint32_t)__cvta_generic_to_shared(p);
}
#define CP16(dst_u32, src_ptr) \
    asm volatile("cp.async.cg.shared.global [%0], [%1], 16;" :: "r"(dst_u32), "l"(src_ptr) : "memory")
#define CP_COMMIT() asm volatile("cp.async.commit_group;" ::: "memory")
#define CP_WAIT0()  asm volatile("cp.async.wait_group 0;" ::: "memory")
#define CP_WAIT1()  asm volatile("cp.async.wait_group 1;" ::: "memory")

#define MMA_F16(d, a, b) \
    asm volatile("mma.sync.aligned.m16n8k16.row.col.f32.f16.f16.f32 " \
        "{%0,%1,%2,%3},{%4,%5,%6,%7},{%8,%9},{%0,%1,%2,%3};" \
        : "+f"((d)[0]), "+f"((d)[1]), "+f"((d)[2]), "+f"((d)[3]) \
        : "r"((a)[0]), "r"((a)[1]), "r"((a)[2]), "r"((a)[3]), "r"((b)[0]), "r"((b)[1]))

#define LDM4(r0, r1, r2, r3, addr) \
    asm volatile("ldmatrix.sync.aligned.m8n8.x4.shared.b16 {%0,%1,%2,%3}, [%4];" \
        : "=r"(r0), "=r"(r1), "=r"(r2), "=r"(r3) : "r"(addr))

__device__ __forceinline__ uint32_t pack_hi2(float x0, float x1) {
    __half2 t(__float2half_rn(x0), __float2half_rn(x1));
    return *reinterpret_cast<uint32_t*>(&t);
}

// ---------------- prep kernels -------------------------------------------------------
__global__ void mel_split_kernel(const float* __restrict__ mels) {
    size_t i = (size_t)blockIdx.x * blockDim.x + threadIdx.x;
    if (i < (size_t)BB * TT * 96) {
        size_t t = i / 96;
        int ci = (int)(i % 96);
        float x = (ci < NMEL) ? mels[t * NMEL + ci] : 0.f;
        g_melhi[i] = __float2half_rn(x);
    }
}
__global__ void wsplit_both_kernel(const float* __restrict__ w1,
                                   const float* __restrict__ w2) {
    const int N1 = KK * FILT * 96;
    const int N2 = KK * FILT * FILT;
    int i = blockIdx.x * blockDim.x + threadIdx.x;
    if (i < N1) {
        int ci = i % 96, co = (i / 96) % FILT, tap = i / (96 * FILT);
        float x = (ci < NMEL) ? w1[(co * NMEL + ci) * KK + tap] : 0.f;
        g_w1h[i] = __float2half_rn(x);
    } else if (i - N1 < N2) {
        int j = i - N1;
        int ci = j % FILT, co = (j / FILT) % FILT, tap = j / (FILT * FILT);
        g_w2h[j] = __float2half_rn(w2[(co * FILT + ci) * KK + tap]);
    }
}
__global__ void scan_kernel(const int* __restrict__ dur, const int* __restrict__ wpl) {
    int b = blockIdx.x, lane = threadIdx.x;
    int v[16], s = 0;
#pragma unroll
    for (int i = 0; i < 16; i++) { v[i] = dur[b * PP + lane * 16 + i]; s += v[i]; }
    int inc = s;
#pragma unroll
    for (int off = 1; off < 32; off <<= 1) {
        int t = __shfl_up_sync(0xffffffffu, inc, off);
        if (lane >= off) inc += t;
    }
    int base = inc - s, run = 0;
#pragma unroll
    for (int i = 0; i < 16; i++) { run += v[i]; g_pcum[b * PP + lane * 16 + i] = base + run; }
    int w[4]; s = 0;
#pragma unroll
    for (int i = 0; i < 4; i++) { w[i] = wpl[b * WW + lane * 4 + i]; s += w[i]; }
    inc = s;
#pragma unroll
    for (int off = 1; off < 32; off <<= 1) {
        int t = __shfl_up_sync(0xffffffffu, inc, off);
        if (lane >= off) inc += t;
    }
    base = inc - s; run = 0;
#pragma unroll
    for (int i = 0; i < 4; i++) { run += w[i]; g_wcum[b * WW + lane * 4 + i] = base + run; }
}

// ---------------- conv1 fused: fp16 mma + bias + relu + LN -> fp16 hi ----------------
// M=64 x N=256, 8 warps (2m x 4n), 2 CTAs/SM. Single K-chunk of 80 channels; 9 stages.
__global__ void __launch_bounds__(256, 2) conv1_fused(
    const __half* __restrict__ Ahi, const __half* __restrict__ Bh16,
    const float* __restrict__ bias, const float* __restrict__ gamma,
    const float* __restrict__ beta, __half* __restrict__ outh)
{
    constexpr int CINP = 96, NST = KK;   // 9 stages, tap-major
    extern __shared__ __half smhf[];
    __shared__ float sB[FILT], sG[FILT], sE[FILT];
    __shared__ float s_m[64], s_r[64];

    const int tid = threadIdx.x;
    const int wid = tid >> 5, lane = tid & 31;
    const int wm = wid & 1, wn = wid >> 1;
    const int t0 = blockIdx.x * 64;
    const size_t bT = (size_t)blockIdx.y * TT;
    const uint32_t smb = smem_u32(smhf);

    if (tid < FILT) { sB[tid] = bias[tid]; sG[tid] = gamma[tid]; sE[tid] = beta[tid]; }

    float acc[2][8][4];
#pragma unroll
    for (int mt = 0; mt < 2; mt++)
#pragma unroll
        for (int nt = 0; nt < 8; nt++)
#pragma unroll
            for (int q = 0; q < 4; q++) acc[mt][nt][q] = 0.f;

    const int a_l = ((lane >> 3) & 1) * 8 + (lane & 7);
    const int a_k = (lane >> 4) * 8;
    const int b_l = (lane >> 4) * 8 + (lane & 7);
    const int b_k = ((lane >> 3) & 1) * 8;
    uint32_t aoff[2], boff[4];
#pragma unroll
    for (int mt = 0; mt < 2; mt++)
        aoff[mt] = ((wm * 32 + mt * 16 + a_l) * C1_STR + a_k) * 2;
#pragma unroll
    for (int np = 0; np < 4; np++)
        boff[np] = ((wn * 64 + np * 16 + b_l) * C1_STR + b_k) * 2;

    // B loads: thread = output-channel row, 10 contiguous CP16 (80 channels).
    auto issue_loads = [&](int s) {
        int tap = s;
        __half* sBp = smhf + C1_OFFB + (s & 1) * C1_BCP;
        __half* dB = sBp + tid * C1_STR;
        const __half* srcB = Bh16 + ((size_t)tap * FILT + tid) * CINP;
#pragma unroll
        for (int j = 0; j < 10; j++)
            CP16(smem_u32(dB + j * 8), srcB + j * 8);
        if (tap == 0 && tid < C1_AROWS) {
            int trow = t0 + tid - PAD;
            __half* dA = smhf + tid * C1_STR;
            if (trow >= 0 && trow < TT) {
                const __half* srcA = Ahi + (bT + trow) * CINP;
#pragma unroll
                for (int j = 0; j < 10; j++)
                    CP16(smem_u32(dA + j * 8), srcA + j * 8);
            } else {
#pragma unroll
                for (int j = 0; j < 10; j++)
                    *(uint4*)(dA + j * 8) = make_uint4(0, 0, 0, 0);
            }
        }
    };

    issue_loads(0); CP_COMMIT();

    for (int s = 0; s < NST; s++) {
        CP_WAIT0();
        __syncthreads();
        if (s + 1 < NST) { issue_loads(s + 1); CP_COMMIT(); }

        uint32_t aAh = smb + s * (C1_STR * 2);               // tap shifts A row
        uint32_t aB  = smb + (C1_OFFB + (s & 1) * C1_BCP) * 2;

#pragma unroll
        for (int kk = 0; kk < 5; kk++) {
            uint32_t ah[2][4], bh[8][2];
#pragma unroll
            for (int mt = 0; mt < 2; mt++)
                LDM4(ah[mt][0], ah[mt][1], ah[mt][2], ah[mt][3], aAh + aoff[mt] + kk * 32);
#pragma unroll
            for (int np = 0; np < 4; np++)
                LDM4(bh[2 * np][0], bh[2 * np][1], bh[2 * np + 1][0], bh[2 * np + 1][1],
                     aB + boff[np] + kk * 32);
#pragma unroll
            for (int mt = 0; mt < 2; mt++)
#pragma unroll
                for (int nt = 0; nt < 8; nt++) MMA_F16(acc[mt][nt], ah[mt], bh[nt]);
        }
    }
    __syncthreads();

    // epilogue: bias+relu -> smem (64x256 fp32), LN, write fp16 hi
    float* st = (float*)smhf;
    const int r = lane >> 2, cq = lane & 3;
#pragma unroll
    for (int mt = 0; mt < 2; mt++) {
        int R0 = wm * 32 + mt * 16 + r;
#pragma unroll
        for (int nt = 0; nt < 8; nt++) {
            int C = wn * 64 + nt * 8 + 2 * cq;
            st[R0 * FILT + C]           = fmaxf(acc[mt][nt][0] + sB[C], 0.f);
            st[R0 * FILT + C + 1]       = fmaxf(acc[mt][nt][1] + sB[C + 1], 0.f);
            st[(R0 + 8) * FILT + C]     = fmaxf(acc[mt][nt][2] + sB[C], 0.f);
            st[(R0 + 8) * FILT + C + 1] = fmaxf(acc[mt][nt][3] + sB[C + 1], 0.f);
        }
    }
    __syncthreads();

#pragma unroll
    for (int rr = 0; rr < 8; rr++) {
        int row = wid * 8 + rr;
        float4 u = ((const float4*)st)[row * 64 + lane];
        float4 v = ((const float4*)st)[row * 64 + lane + 32];
        float s = u.x + u.y + u.z + u.w + v.x + v.y + v.z + v.w;
        float q = u.x * u.x + u.y * u.y + u.z * u.z + u.w * u.w
                + v.x * v.x + v.y * v.y + v.z * v.z + v.w * v.w;
#pragma unroll
        for (int off = 16; off > 0; off >>= 1) {
            s += __shfl_xor_sync(0xffffffffu, s, off);
            q += __shfl_xor_sync(0xffffffffu, q, off);
        }
        if (lane == 0) {
            float m = s * (1.f / FILT);
            s_m[row] = m;
            s_r[row] = rsqrtf(q * (1.f / FILT) - m * m + 1e-5f);
        }
    }
    __syncthreads();

#pragma unroll
    for (int j = 0; j < 16; j++) {
        int f4 = tid + j * 256;               // 4096 float4 = 64x256
        int row = f4 >> 6, c4 = f4 & 63;
        float4 v = ((const float4*)st)[f4];
        float m = s_m[row], rs = s_r[row];
        int C = c4 * 4;
        float y0 = (v.x - m) * rs * sG[C]     + sE[C];
        float y1 = (v.y - m) * rs * sG[C + 1] + sE[C + 1];
        float y2 = (v.z - m) * rs * sG[C + 2] + sE[C + 2];
        float y3 = (v.w - m) * rs * sG[C + 3] + sE[C + 3];
        size_t o = (bT + t0 + row) * FILT + C;
        *(uint2*)(outh + o) = make_uint2(pack_hi2(y0, y1), pack_hi2(y2, y3));
    }
}

// ---------------- conv2: fp16 mma, M=128 x N=128, K-chunk 64; bias+relu -> fp16 ------
__global__ void __launch_bounds__(256, 2) conv2_mma(
    const __half* __restrict__ Ahi, const __half* __restrict__ Bh16,
    const float* __restrict__ bias, __half* __restrict__ outh)
{
    constexpr int CINP = FILT, NST = 4 * KK;   // 36 stages
    extern __shared__ __half smhf[];

    const int tid = threadIdx.x;
    const int wid = tid >> 5, lane = tid & 31;
    const int wm = wid & 1, wn = wid >> 1;
    const int t0 = blockIdx.x * 128;
    const int n0 = blockIdx.y * 128;
    const size_t bT = (size_t)blockIdx.z * TT;
    const uint32_t smb = smem_u32(smhf);

    float acc[4][4][4];
#pragma unroll
    for (int mt = 0; mt < 4; mt++)
#pragma unroll
        for (int nt = 0; nt < 4; nt++)
#pragma unroll
            for (int q = 0; q < 4; q++) acc[mt][nt][q] = 0.f;

    const int a_l = ((lane >> 3) & 1) * 8 + (lane & 7);
    const int a_k = (lane >> 4) * 8;
    const int b_l = (lane >> 4) * 8 + (lane & 7);
    const int b_k = ((lane >> 3) & 1) * 8;
    uint32_t aoff[4], boff[2];
#pragma unroll
    for (int mt = 0; mt < 4; mt++)
        aoff[mt] = ((wm * 64 + mt * 16 + a_l) * STR2 + a_k) * 2;
#pragma unroll
    for (int np = 0; np < 2; np++)
        boff[np] = ((wn * 32 + np * 16 + b_l) * STR2 + b_k) * 2;

    auto issue_loads = [&](int s) {
        int chunk = s / KK, tap = s - chunk * KK;
        __half* sB = smhf + OFF_B2 + (s % 3) * B_CP2;
#pragma unroll
        for (int j = 0; j < 4; j++) {
            int q = tid + j * 256;                      // 128 rows x 8 c16 = 1024
            int row = q >> 3, c16 = q & 7;
            const __half* src = Bh16
                + ((size_t)tap * FILT + n0 + row) * CINP + chunk * 64 + c16 * 8;
            CP16(smem_u32(sB + row * STR2 + c16 * 8), src);
        }
        if (tap == 0) {
            __half* sA = smhf + (chunk & 1) * A_CP2;
#pragma unroll
            for (int j = 0; j < 5; j++) {
                int q = tid + j * 256;
                if (q < 8 * A_ROWS) {                   // 1088
                    int row = q >> 3, c16 = q & 7;
                    int trow = t0 + row - PAD;
                    __half* dst = sA + row * STR2 + c16 * 8;
                    if (trow >= 0 && trow < TT) {
                        const __half* src = Ahi
                            + (bT + trow) * CINP + chunk * 64 + c16 * 8;
                        CP16(smem_u32(dst), src);
                    } else {
                        *(uint4*)dst = make_uint4(0, 0, 0, 0);
                    }
                }
            }
        }
    };

    issue_loads(0); CP_COMMIT();
    issue_loads(1); CP_COMMIT();

    for (int s = 0; s < NST; s++) {
        if (s + 1 < NST) CP_WAIT1(); else CP_WAIT0();
        __syncthreads();
        if (s + 2 < NST) { issue_loads(s + 2); CP_COMMIT(); }

        int chunk = s / KK, tap = s - chunk * KK;
        uint32_t aAh = smb + (chunk & 1) * (A_CP2 * 2) + tap * (STR2 * 2);
        uint32_t aBh = smb + (OFF_B2 + (s % 3) * B_CP2) * 2;

#pragma unroll
        for (int kk = 0; kk < 4; kk++) {
            uint32_t ah[4][4], bh[4][2];
#pragma unroll
            for (int mt = 0; mt < 4; mt++)
                LDM4(ah[mt][0], ah[mt][1], ah[mt][2], ah[mt][3], aAh + aoff[mt] + kk * 32);
#pragma unroll
            for (int np = 0; np < 2; np++)
                LDM4(bh[2 * np][0], bh[2 * np][1], bh[2 * np + 1][0], bh[2 * np + 1][1],
                     aBh + boff[np] + kk * 32);
#pragma unroll
            for (int mt = 0; mt < 4; mt++)
#pragma unroll
                for (int nt = 0; nt < 4; nt++) MMA_F16(acc[mt][nt], ah[mt], bh[nt]);
        }
    }
    __syncthreads();

    // epilogue: stage acc to smem; then bias+relu -> fp16 global
    float* st = (float*)smhf;
    const int r = lane >> 2, cq = lane & 3;
#pragma unroll
    for (int mt = 0; mt < 4; mt++) {
        int R0 = wm * 64 + mt * 16 + r;
#pragma unroll
        for (int nt = 0; nt < 4; nt++) {
            int C = wn * 32 + nt * 8 + 2 * cq;
            st[R0 * 128 + C]           = acc[mt][nt][0];
            st[R0 * 128 + C + 1]       = acc[mt][nt][1];
            st[(R0 + 8) * 128 + C]     = acc[mt][nt][2];
            st[(R0 + 8) * 128 + C + 1] = acc[mt][nt][3];
        }
    }
    __syncthreads();
    {
        int c4 = tid & 31;
        float b0 = bias[n0 + c4 * 4];
        float b1 = bias[n0 + c4 * 4 + 1];
        float b2 = bias[n0 + c4 * 4 + 2];
        float b3 = bias[n0 + c4 * 4 + 3];
#pragma unroll
        for (int i = 0; i < 16; i++) {
            int f4 = tid + i * 256;
            int row = f4 >> 5;
            float4 v = ((const float4*)st)[f4];
            float y0 = fmaxf(v.x + b0, 0.f), y1 = fmaxf(v.y + b1, 0.f);
            float y2 = fmaxf(v.z + b2, 0.f), y3 = fmaxf(v.w + b3, 0.f);
            *(uint2*)(outh + (bT + t0 + row) * FILT + n0 + c4 * 4) =
                make_uint2(pack_hi2(y0, y1), pack_hi2(y2, y3));
        }
    }
}

// ---------------- fused LN + phone mean pool (warp-per-frame) ------------------------
__global__ void __launch_bounds__(256) lnpool_kernel(
    const int* __restrict__ dur, const __half* __restrict__ gc,
    const float* __restrict__ gamma, const float* __restrict__ beta)
{
    __shared__ float sG[FILT], sE[FILT];
    __shared__ float red[8 * FILT];
    int b = blockIdx.y, p = blockIdx.x, tid = threadIdx.x;
    int w = tid >> 5, lane = tid & 31;
    sG[tid] = gamma[tid]; sE[tid] = beta[tid];
    __syncthreads();

    int start = p ? g_pcum[b * PP + p - 1] : 0;
    int end = g_pcum[b * PP + p];
    if (start > TT) start = TT;
    if (end > TT) end = TT;

    int c0 = lane * 8;
    float a[8];
#pragma unroll
    for (int j = 0; j < 8; j++) a[j] = 0.f;

    for (int t = start + w; t < end; t += 8) {
        uint4 u = *(const uint4*)(gc + ((size_t)(b * TT + t)) * FILT + c0);
        const __half2* hp = (const __half2*)&u;
        float x[8];
#pragma unroll
        for (int j = 0; j < 4; j++) {
            float2 f = __half22float2(hp[j]);
            x[2 * j] = f.x; x[2 * j + 1] = f.y;
        }
        float s = 0.f, q = 0.f;
#pragma unroll
        for (int j = 0; j < 8; j++) { s += x[j]; q += x[j] * x[j]; }
#pragma unroll
        for (int off = 16; off > 0; off >>= 1) {
            s += __shfl_xor_sync(0xffffffffu, s, off);
            q += __shfl_xor_sync(0xffffffffu, q, off);
        }
        float m = s * (1.f / FILT);
        float rs = rsqrtf(q * (1.f / FILT) - m * m + 1e-5f);
#pragma unroll
        for (int j = 0; j < 8; j++)
            a[j] += (x[j] - m) * rs * sG[c0 + j] + sE[c0 + j];
    }
#pragma unroll
    for (int j = 0; j < 8; j++) red[w * FILT + c0 + j] = a[j];
    __syncthreads();

    int c = tid;
    float sum = 0.f;
#pragma unroll
    for (int w8 = 0; w8 < 8; w8++) sum += red[w8 * FILT + c];
    int d = dur[b * PP + p]; if (d < 1) d = 1;
    g_ph[((size_t)(b * PP + p)) * FILT + c] = sum / (float)d;
}

// ---------------- word pool / mlp / expand ------------------------------------------
__global__ void word_pool_kernel(const int* __restrict__ wpl) {
    int b = blockIdx.y, w = blockIdx.x, c = threadIdx.x;
    int start = w ? g_wcum[b * WW + w - 1] : 0;
    int end = g_wcum[b * WW + w];
    if (start > PP) start = PP;
    if (end > PP) end = PP;
    float s = 0.f;
    for (int p = start; p < end; p++) s += g_ph[((size_t)(b * PP + p)) * FILT + c];
    int d = wpl[b * WW + w]; if (d < 1) d = 1;
    g_wd[((size_t)(b * WW + w)) * FILT + c] = s / (float)d;
}
__global__ void __launch_bounds__(256) mlp_kernel(
    const float* __restrict__ w1, const float* __restrict__ b1,
    const float* __restrict__ w2, const float* __restrict__ b2)
{
    __shared__ float sh[32 * FILT];
    int b = blockIdx.y, w0 = blockIdx.x * 32, o = threadIdx.x;
    for (int idx = o; idx < 32 * FILT; idx += 256)
        sh[idx] = g_wd[((size_t)(b * WW + w0)) * FILT + idx];
    __syncthreads();
    float acc[32];
    float bv = b1[o];
#pragma unroll
    for (int m = 0; m < 32; m++) acc[m] = bv;
    for (int i = 0; i < FILT; i++) {
        float wv = w1[i * FILT + o];
#pragma unroll
        for (int m = 0; m < 32; m++) acc[m] += sh[m * FILT + i] * wv;
    }
    __syncthreads();
#pragma unroll
    for (int m = 0; m < 32; m++) sh[m * FILT + o] = fmaxf(acc[m], 0.f);
    __syncthreads();
    int oo = o & (PDIM - 1);
    int mg = o >> 6;
    for (int m = mg * 8; m < mg * 8 + 8; m++) {
        float a = b2[oo];
        for (int i = 0; i < FILT; i++) a += sh[m * FILT + i] * w2[i * PDIM + oo];
        g_z[((size_t)(b * WW + w0 + m)) * PDIM + oo] = fmaxf(a, 0.f);
    }
}
__global__ void expand_kernel(const unsigned char* __restrict__ mask, float* __restrict__ out) {
    int b = blockIdx.y, p = blockIdx.x, o = threadIdx.x;
    const int* wc = g_wcum + b * WW;
    int lo = 0, hi = WW;
    while (lo < hi) { int mid = (lo + hi) >> 1; if (wc[mid] <= p) lo = mid + 1; else hi = mid; }
    int wid = lo; if (wid > WW - 1) wid = WW - 1;
    float v = g_z[((size_t)(b * WW + wid)) * PDIM + o];
    if (mask[b * PP + p]) v = 0.f;
    out[((size_t)(b * PP + p)) * PDIM + o] = v;
}

// ---------------- host launch -------------------------------------------------------
extern "C" void kernel_launch(void* const* d_in, const int* in_sizes, int n_in,
                              void* d_out, int out_size)
{
    const unsigned char* mask = (const unsigned char*)d_in[0];
    const float* mels = (const float*)d_in[1];
    const int* durations = (const int*)d_in[3];
    const int* wpl = (const int*)d_in[4];
    const float* c1w = (const float*)d_in[5];
    const float* c1b = (const float*)d_in[6];
    const float* l1g = (const float*)d_in[7];
    const float* l1b = (const float*)d_in[8];
    const float* c2w = (const float*)d_in[9];
    const float* c2b = (const float*)d_in[10];
    const float* l2g = (const float*)d_in[11];
    const float* l2b = (const float*)d_in[12];
    const float* w1 = (const float*)d_in[13];
    const float* b1 = (const float*)d_in[14];
    const float* w2 = (const float*)d_in[15];
    const float* b2 = (const float*)d_in[16];
    float* out = (float*)d_out;

    void *p_melhi, *p_x1hi, *p_craw, *p_w1h, *p_w2h;
    cudaGetSymbolAddress(&p_melhi, g_melhi);
    cudaGetSymbolAddress(&p_x1hi, g_x1hi);
    cudaGetSymbolAddress(&p_craw, g_craw);
    cudaGetSymbolAddress(&p_w1h, g_w1h);
    cudaGetSymbolAddress(&p_w2h, g_w2h);

    cudaFuncSetAttribute(conv1_fused, cudaFuncAttributeMaxDynamicSharedMemorySize, CONV1_SMEM);
    cudaFuncSetAttribute(conv2_mma, cudaFuncAttributeMaxDynamicSharedMemorySize, CONV2_SMEM);

    mel_split_kernel<<<(int)(((size_t)BB * TT * 96 + 255) / 256), 256>>>(mels);
    wsplit_both_kernel<<<(KK * FILT * (96 + FILT) + 255) / 256, 256>>>(c1w, c2w);
    scan_kernel<<<BB, 32>>>(durations, wpl);

    conv1_fused<<<dim3(TT / 64, BB), 256, CONV1_SMEM>>>(
        (const __half*)p_melhi, (const __half*)p_w1h,
        c1b, l1g, l1b, (__half*)p_x1hi);
    conv2_mma<<<dim3(TT / 128, 2, BB), 256, CONV2_SMEM>>>(
        (const __half*)p_x1hi, (const __half*)p_w2h, c2b, (__half*)p_craw);

    lnpool_kernel<<<dim3(PP, BB), FILT>>>(durations, (const __half*)p_craw, l2g, l2b);
    word_pool_kernel<<<dim3(WW, BB), FILT>>>(wpl);
    mlp_kernel<<<dim3(WW / 32, BB), 256>>>(w1, b1, w2, b2);
    expand_kernel<<<dim3(PP, BB), PDIM>>>(mask, out);
}